// round 1
// baseline (speedup 1.0000x reference)
#include <cuda_runtime.h>
#include <cuda_bf16.h>

// V=100000, K=32, F=64.
// out[v, 0:64]   = mean over K neighbours of x[idxs[v,k], :]
// out[v, 64:128] = max  over K neighbours
//
// One warp per vertex. x viewed as float2 rows of 32 elements: lane l owns
// element l of every gathered row -> one coalesced 256B request per row.
// x (25.6MB) lives in L2; kernel is LTS-throughput bound.

#define KNN 32
#define FDIM 64

__global__ __launch_bounds__(256)
void knn_mean_max_kernel(const float2* __restrict__ x2,
                         const int*    __restrict__ idxs,
                         float2*       __restrict__ out2,
                         int V)
{
    const int warp = (blockIdx.x * blockDim.x + threadIdx.x) >> 5;
    const int lane = threadIdx.x & 31;
    if (warp >= V) return;

    // Coalesced index load: lane l holds idxs[warp][l]
    const int my_idx = idxs[warp * KNN + lane];

    float2 s = make_float2(0.0f, 0.0f);
    float2 m = make_float2(-3.402823466e+38f, -3.402823466e+38f);

    // Full unroll: ptxas front-batches the gather loads for high MLP.
    #pragma unroll
    for (int k = 0; k < KNN; ++k) {
        const int idx = __shfl_sync(0xffffffffu, my_idx, k);
        const float2 v = __ldg(&x2[idx * (FDIM / 2) + lane]);
        s.x += v.x;  s.y += v.y;
        m.x = fmaxf(m.x, v.x);
        m.y = fmaxf(m.y, v.y);
    }

    s.x *= (1.0f / KNN);
    s.y *= (1.0f / KNN);

    // Output row = 128 floats = 64 float2: [mean(32 float2) | max(32 float2)]
    out2[warp * (FDIM) + lane]        = s;   // FDIM=64 float2 per out row
    out2[warp * (FDIM) + 32 + lane]   = m;
}

extern "C" void kernel_launch(void* const* d_in, const int* in_sizes, int n_in,
                              void* d_out, int out_size)
{
    const float2* x2   = (const float2*)d_in[0];  // x: [V, 64] float32
    const int*    idxs = (const int*)d_in[1];     // idxs: [V, 32] int32
    float2*       out2 = (float2*)d_out;          // out: [V, 128] float32

    const int V = in_sizes[0] / FDIM;             // 100000
    const int warps_per_block = 256 / 32;         // 8
    const int blocks = (V + warps_per_block - 1) / warps_per_block;

    knn_mean_max_kernel<<<blocks, 256>>>(x2, idxs, out2, V);
}